// round 8
// baseline (speedup 1.0000x reference)
#include <cuda_runtime.h>
#include <cuda_fp16.h>
#include <math.h>
#include <stdint.h>

#define B_ 64
#define F_ 32
#define S_ 512
#define P_ 96
#define E_ 8
#define H_ 2048
#define T_ (F_*B_)   /* 2048 tokens */
#define ALPHA 10.0f
#define ENT_EPS 1e-8f
#define CV_EPS 1e-10f
#define KS4 4        /* gemm2 k-split */

// ---- scratch (device globals: allocation-free) ----
__device__ __half g_xf[(size_t)T_ * S_];           // 2 MB   token-major x (fp16)
__device__ __half g_w1t[(size_t)E_ * H_ * S_];     // 16.8MB W1^T [e][h][s] (fp16)
__device__ __half g_w2t[(size_t)E_ * P_ * H_];     // 3.1 MB W2^T [e][p][h] (fp16)
__device__ float  g_gates[T_ * E_];                // 64 KB
__device__ __half g_h[(size_t)E_ * T_ * H_];       // 67 MB  gelu(x@W1+b1) (fp16)
__device__ float  g_eo[(size_t)E_ * KS4 * T_ * P_];// 25 MB  expert output partials

// ==================================================================
// helpers
// ==================================================================
__device__ __forceinline__ uint32_t smem_u32(const void* p) {
    uint32_t a;
    asm("{ .reg .u64 t; cvta.to.shared.u64 t, %1; cvt.u32.u64 %0, t; }"
        : "=r"(a) : "l"(p));
    return a;
}
__device__ __forceinline__ void cp16(uint32_t saddr, const void* gaddr) {
    asm volatile("cp.async.cg.shared.global [%0], [%1], 16;"
                 :: "r"(saddr), "l"(gaddr) : "memory");
}
#define CP_COMMIT() asm volatile("cp.async.commit_group;" ::: "memory")
#define CP_WAIT2()  asm volatile("cp.async.wait_group 2;" ::: "memory")

__device__ __forceinline__ void mma16(float* d, const uint32_t* a, const uint32_t* b) {
    asm volatile(
        "mma.sync.aligned.m16n8k16.row.col.f32.f16.f16.f32 "
        "{%0,%1,%2,%3}, {%4,%5,%6,%7}, {%8,%9}, {%0,%1,%2,%3};"
        : "+f"(d[0]), "+f"(d[1]), "+f"(d[2]), "+f"(d[3])
        : "r"(a[0]), "r"(a[1]), "r"(a[2]), "r"(a[3]), "r"(b[0]), "r"(b[1]));
}
__device__ __forceinline__ void ldsm4(uint32_t* r, uint32_t addr) {
    asm volatile("ldmatrix.sync.aligned.m8n8.x4.shared.b16 {%0,%1,%2,%3}, [%4];"
                 : "=r"(r[0]), "=r"(r[1]), "=r"(r[2]), "=r"(r[3]) : "r"(addr));
}
__device__ __forceinline__ float gelu_f(float v) {
    return 0.5f * v * (1.f + erff(v * 0.70710678118f));
}

// smem pitch: 40 halves (80 B) per 32-half row -> conflict-free (scalar + ldmatrix)
#define PITCH 40

// ==================================================================
// 1) fused prep + gates:
//    x->g_xf        blocks [0, 1024)
//    W1^T           blocks [1024, 9216)
//    W2^T           blocks [9216, 10752)
//    gates          blocks [10752, 11008)   (8 tokens per block)
// ==================================================================
#define PREP_XF_BLKS 1024
#define PREP_W1_BLKS (64 * 16 * E_)     /* 8192 */
#define PREP_W2_BLKS (3 * 64 * E_)      /* 1536 */
#define PREP_BLKS (PREP_XF_BLKS + PREP_W1_BLKS + PREP_W2_BLKS)
#define GATES_BLKS (T_ / 8)             /* 256 */
#define PREP_TOTAL (PREP_BLKS + GATES_BLKS)
__global__ void __launch_bounds__(256) prep_all(const float* __restrict__ x,
                                                const float* __restrict__ W1,
                                                const float* __restrict__ W2,
                                                const float* __restrict__ te,
                                                const float* __restrict__ Wg,
                                                const float* __restrict__ bg) {
    __shared__ float tile[32][33];
    __shared__ float s_wg[S_ * 9];       // gates branch only (18 KB)
    int bid = blockIdx.x;
    if (bid < PREP_XF_BLKS) {
        int t = bid * 2 + (threadIdx.x >> 7);
        int tl = threadIdx.x & 127;
        int f = t / B_, b = t - f * B_;
        const float4* src = (const float4*)(x + ((size_t)b * F_ + f) * S_);
        float4 v = src[tl];
        __half2* dst = (__half2*)(g_xf + (size_t)t * S_) + tl * 2;
        dst[0] = __floats2half2_rn(v.x, v.y);
        dst[1] = __floats2half2_rn(v.z, v.w);
    } else if (bid < PREP_XF_BLKS + PREP_W1_BLKS) {
        int i = bid - PREP_XF_BLKS;
        int e = i >> 10;                 // 64*16 per expert
        int r = i & 1023;
        int h0 = (r & 63) * 32, s0 = (r >> 6) * 32;
        int lx = threadIdx.x & 31, ly = threadIdx.x >> 5;    // 32 x 8
        #pragma unroll
        for (int k = 0; k < 32; k += 8)
            tile[ly + k][lx] = W1[((size_t)e * S_ + s0 + ly + k) * H_ + h0 + lx];
        __syncthreads();
        #pragma unroll
        for (int k = 0; k < 32; k += 8)
            g_w1t[((size_t)e * H_ + h0 + ly + k) * S_ + s0 + lx] = __float2half_rn(tile[lx][ly + k]);
    } else if (bid < PREP_BLKS) {
        int i = bid - PREP_XF_BLKS - PREP_W1_BLKS;
        int e = i / 192;
        int r = i % 192;
        int p0 = (r % 3) * 32, h0 = (r / 3) * 32;
        int lx = threadIdx.x & 31, ly = threadIdx.x >> 5;
        #pragma unroll
        for (int k = 0; k < 32; k += 8)
            tile[ly + k][lx] = W2[((size_t)e * H_ + h0 + ly + k) * P_ + p0 + lx];
        __syncthreads();
        #pragma unroll
        for (int k = 0; k < 32; k += 8)
            g_w2t[((size_t)e * P_ + p0 + ly + k) * H_ + h0 + lx] = __float2half_rn(tile[lx][ly + k]);
    } else {
        // ---- gates: 8 tokens, one warp per token ----
        const int tid = threadIdx.x;
        #pragma unroll
        for (int k = 0; k < 16; k++) {
            int idx = tid + 256 * k;     // 4096
            s_wg[(idx >> 3) * 9 + (idx & 7)] = Wg[idx];
        }
        __syncthreads();

        const int w = tid >> 5, lane = tid & 31;
        const int tok = (bid - PREP_BLKS) * 8 + w;
        const int f = tok / B_, b = tok - f * B_;
        const float* row = te + ((size_t)b * F_ + f) * S_;

        float acc[E_];
        #pragma unroll
        for (int e = 0; e < E_; e++) acc[e] = 0.f;
        #pragma unroll
        for (int c = 0; c < 16; c++) {
            float v = row[c * 32 + lane];
            const float* wp = s_wg + (c * 32 + lane) * 9;
            #pragma unroll
            for (int e = 0; e < E_; e++) acc[e] += v * wp[e];
        }
        #pragma unroll
        for (int e = 0; e < E_; e++)
            #pragma unroll
            for (int o = 16; o > 0; o >>= 1)
                acc[e] += __shfl_xor_sync(0xffffffffu, acc[e], o);

        if (lane == 0) {
            float lg[E_];
            float m1 = -1e30f, m2 = -1e30f;
            #pragma unroll
            for (int i = 0; i < E_; i++) {
                float v = acc[i] + bg[i]; lg[i] = v;
                if (v > m1) { m2 = m1; m1 = v; } else if (v > m2) m2 = v;
            }
            float kth = m2;
            float smv[E_]; float se = 0.f;
            #pragma unroll
            for (int i = 0; i < E_; i++) { smv[i] = expf(lg[i] - m1); se += smv[i]; }
            float inv = 1.f / se;
            float dec[E_]; float mx2 = -1e30f;
            #pragma unroll
            for (int i = 0; i < E_; i++) {
                float smi = smv[i] * inv;
                float d = (lg[i] < kth) ? ALPHA * logf(smi + 1.f)
                                        : ALPHA * (expf(smi) - 1.f);
                dec[i] = d; if (d > mx2) mx2 = d;
            }
            float s2 = 0.f;
            #pragma unroll
            for (int i = 0; i < E_; i++) { dec[i] = expf(dec[i] - mx2); s2 += dec[i]; }
            float inv2 = 1.f / s2;
            #pragma unroll
            for (int i = 0; i < E_; i++) g_gates[tok * E_ + i] = dec[i] * inv2;
        }
    }
}

// ==================================================================
// 4) GEMM1 (HMMA + ldmatrix): h = gelu(Xf @ W1t^T + b1)
//    block 128M x 128N x 32K, 4-stage, 8 warps (2m x 4n), warp 64x32
//    80 KB smem -> 2 CTAs/SM
// ==================================================================
#define G1_B_OFF (128 * PITCH * 2)                  /* bytes */
#define G1_STAGE_B (2 * 128 * PITCH * 2)            /* 20480 bytes */
#define G1_SMEM (4 * G1_STAGE_B)
__global__ void __launch_bounds__(256, 2) gemm1_tc(const float* __restrict__ b1) {
    extern __shared__ __half smh[];
    const int tid = threadIdx.x;
    const int wid = tid >> 5, lane = tid & 31;
    const int g = lane >> 2, q = lane & 3;
    const int e = blockIdx.z;
    const int bm = blockIdx.y * 128, bn = blockIdx.x * 128;
    const int wm = (wid & 1) * 64, wn = (wid >> 1) * 32;
    const uint32_t smb = smem_u32(smh);

    const __half* gA = g_xf + (size_t)bm * S_;
    const __half* gB = g_w1t + ((size_t)e * H_ + bn) * S_;

    uint32_t aoff[4], boff[2];
    {
        const int lrA = lane & 15, lcA = ((lane >> 4) & 1) * 8;
        #pragma unroll
        for (int i = 0; i < 4; i++)
            aoff[i] = (uint32_t)(((wm + i * 16 + lrA) * PITCH + lcA) * 2);
        const int lrB = (lane & 7) + ((lane & 16) >> 1), lcB = lane & 8;
        #pragma unroll
        for (int p = 0; p < 2; p++)
            boff[p] = (uint32_t)(G1_B_OFF + ((wn + p * 16 + lrB) * PITCH + lcB) * 2);
    }

    float acc[4][4][4];
    #pragma unroll
    for (int i = 0; i < 4; i++)
        #pragma unroll
        for (int j = 0; j < 4; j++)
            #pragma unroll
            for (int c = 0; c < 4; c++) acc[i][j][c] = 0.f;

    auto load_stage = [&](int kt, int buf) {
        const uint32_t sA = smb + (uint32_t)buf * G1_STAGE_B;
        const uint32_t sB = sA + G1_B_OFF;
        const int k0 = kt * 32;
        #pragma unroll
        for (int i = 0; i < 2; i++) {
            int idx = tid + 256 * i;
            int r = idx >> 2, c = idx & 3;
            cp16(sA + (uint32_t)r * 80u + (uint32_t)c * 16u,
                 gA + (size_t)r * S_ + k0 + c * 8);
        }
        #pragma unroll
        for (int i = 0; i < 2; i++) {
            int idx = tid + 256 * i;
            int r = idx >> 2, c = idx & 3;
            cp16(sB + (uint32_t)r * 80u + (uint32_t)c * 16u,
                 gB + (size_t)r * S_ + k0 + c * 8);
        }
    };

    const int NKT = S_ / 32;   // 16
    #pragma unroll
    for (int s = 0; s < 3; s++) { load_stage(s, s); CP_COMMIT(); }

    for (int kt = 0; kt < NKT; kt++) {
        CP_WAIT2();
        __syncthreads();
        if (kt + 3 < NKT) load_stage(kt + 3, (kt + 3) & 3);
        CP_COMMIT();
        const uint32_t sbase = smb + (uint32_t)(kt & 3) * G1_STAGE_B;
        #pragma unroll
        for (int ks = 0; ks < 2; ks++) {
            const uint32_t kboff = (uint32_t)(ks * 16 * 2);
            uint32_t a[4][4], bf[2][4];
            #pragma unroll
            for (int i = 0; i < 4; i++) ldsm4(a[i], sbase + aoff[i] + kboff);
            #pragma unroll
            for (int p = 0; p < 2; p++) ldsm4(bf[p], sbase + boff[p] + kboff);
            #pragma unroll
            for (int i = 0; i < 4; i++)
                #pragma unroll
                for (int p = 0; p < 2; p++) {
                    mma16(acc[i][2 * p + 0], a[i], &bf[p][0]);
                    mma16(acc[i][2 * p + 1], a[i], &bf[p][2]);
                }
        }
    }

    const float* bias = b1 + (size_t)e * H_ + bn;
    #pragma unroll
    for (int i = 0; i < 4; i++) {
        int r0 = bm + wm + i * 16 + g;
        #pragma unroll
        for (int j = 0; j < 4; j++) {
            int col = wn + j * 8 + 2 * q;
            float bx = bias[col], by = bias[col + 1];
            __half2 o0 = __floats2half2_rn(gelu_f(acc[i][j][0] + bx),
                                           gelu_f(acc[i][j][1] + by));
            __half2 o1 = __floats2half2_rn(gelu_f(acc[i][j][2] + bx),
                                           gelu_f(acc[i][j][3] + by));
            *(__half2*)(g_h + ((size_t)e * T_ + r0) * H_ + bn + col) = o0;
            *(__half2*)(g_h + ((size_t)e * T_ + r0 + 8) * H_ + bn + col) = o1;
        }
    }
}

// ==================================================================
// 5) GEMM2 (HMMA + ldmatrix, k-split x4): eo[ks] = h[:,ks] @ W2t^T
//    block 128M x 96N x 32K, 4-stage, 8 warps, warp 32x48
// ==================================================================
#define G2_STAGE_H ((128 + 96) * PITCH)
#define G2_B_OFF (128 * PITCH * 2)
#define G2_STAGE_B (G2_STAGE_H * 2)
#define G2_SMEM (4 * G2_STAGE_B)
__global__ void __launch_bounds__(256, 2) gemm2_tc(void) {
    extern __shared__ __half smh[];
    const int tid = threadIdx.x;
    const int wid = tid >> 5, lane = tid & 31;
    const int g = lane >> 2, q = lane & 3;
    const int e = blockIdx.z, ksp = blockIdx.x;
    const int bm = blockIdx.y * 128;
    const int k_base = ksp * (H_ / KS4);
    const int wm = (wid & 3) * 32, wn = (wid >> 2) * 48;
    const uint32_t smb = smem_u32(smh);

    const __half* gA = g_h + ((size_t)e * T_ + bm) * H_ + k_base;
    const __half* gB = g_w2t + (size_t)e * P_ * H_ + k_base;

    uint32_t aoff[2], boff[3];
    {
        const int lrA = lane & 15, lcA = ((lane >> 4) & 1) * 8;
        #pragma unroll
        for (int i = 0; i < 2; i++)
            aoff[i] = (uint32_t)(((wm + i * 16 + lrA) * PITCH + lcA) * 2);
        const int lrB = (lane & 7) + ((lane & 16) >> 1), lcB = lane & 8;
        #pragma unroll
        for (int p = 0; p < 3; p++)
            boff[p] = (uint32_t)(G2_B_OFF + ((wn + p * 16 + lrB) * PITCH + lcB) * 2);
    }

    float acc[2][6][4];
    #pragma unroll
    for (int i = 0; i < 2; i++)
        #pragma unroll
        for (int j = 0; j < 6; j++)
            #pragma unroll
            for (int c = 0; c < 4; c++) acc[i][j][c] = 0.f;

    auto load_stage = [&](int kt, int buf) {
        const uint32_t sA = smb + (uint32_t)buf * G2_STAGE_B;
        const uint32_t sB = sA + G2_B_OFF;
        const int k0 = kt * 32;
        #pragma unroll
        for (int i = 0; i < 2; i++) {
            int idx = tid + 256 * i;
            int r = idx >> 2, c = idx & 3;
            cp16(sA + (uint32_t)r * 80u + (uint32_t)c * 16u,
                 gA + (size_t)r * H_ + k0 + c * 8);
        }
        #pragma unroll
        for (int i = 0; i < 2; i++) {
            int idx = tid + 256 * i;
            if (idx < 384) {
                int r = idx >> 2, c = idx & 3;
                cp16(sB + (uint32_t)r * 80u + (uint32_t)c * 16u,
                     gB + (size_t)r * H_ + k0 + c * 8);
            }
        }
    };

    const int NKT = (H_ / KS4) / 32;   // 16
    #pragma unroll
    for (int s = 0; s < 3; s++) { load_stage(s, s); CP_COMMIT(); }

    for (int kt = 0; kt < NKT; kt++) {
        CP_WAIT2();
        __syncthreads();
        if (kt + 3 < NKT) load_stage(kt + 3, (kt + 3) & 3);
        CP_COMMIT();
        const uint32_t sbase = smb + (uint32_t)(kt & 3) * G2_STAGE_B;
        #pragma unroll
        for (int ks = 0; ks < 2; ks++) {
            const uint32_t kboff = (uint32_t)(ks * 16 * 2);
            uint32_t a[2][4], bf[3][4];
            #pragma unroll
            for (int i = 0; i < 2; i++) ldsm4(a[i], sbase + aoff[i] + kboff);
            #pragma unroll
            for (int p = 0; p < 3; p++) ldsm4(bf[p], sbase + boff[p] + kboff);
            #pragma unroll
            for (int i = 0; i < 2; i++)
                #pragma unroll
                for (int p = 0; p < 3; p++) {
                    mma16(acc[i][2 * p + 0], a[i], &bf[p][0]);
                    mma16(acc[i][2 * p + 1], a[i], &bf[p][2]);
                }
        }
    }

    float* C = g_eo + (size_t)(e * KS4 + ksp) * T_ * P_;
    #pragma unroll
    for (int i = 0; i < 2; i++) {
        int r0 = bm + wm + i * 16 + g;
        #pragma unroll
        for (int j = 0; j < 6; j++) {
            int col = wn + j * 8 + 2 * q;
            float2 o0, o1;
            o0.x = acc[i][j][0]; o0.y = acc[i][j][1];
            o1.x = acc[i][j][2]; o1.y = acc[i][j][3];
            *(float2*)(C + (size_t)r0 * P_ + col) = o0;
            *(float2*)(C + (size_t)(r0 + 8) * P_ + col) = o1;
        }
    }
}

// ==================================================================
// 6) combine (blocks [0,768)) + losses (block 768)
// ==================================================================
__global__ void __launch_bounds__(256) combine_losses(const float* __restrict__ b2,
                                                      float* __restrict__ out,
                                                      float* __restrict__ out_scalars) {
    if (blockIdx.x < (T_ * P_) / 256) {
        int idx = blockIdx.x * 256 + threadIdx.x;
        int t = idx / P_, p = idx - t * P_;
        int f = t / B_, b = t - f * B_;
        float r = 0.f;
        #pragma unroll
        for (int e = 0; e < E_; e++) {
            float v = b2[e * P_ + p];
            #pragma unroll
            for (int ks = 0; ks < KS4; ks++)
                v += g_eo[((size_t)(e * KS4 + ks) * T_ + t) * P_ + p];
            r += g_gates[t * E_ + e] * v;
        }
        out[((size_t)b * F_ + f) * P_ + p] = r;
        return;
    }
    // losses block
    __shared__ float gsum[F_][E_];
    __shared__ float cvf[F_], entf[F_];
    int tid = threadIdx.x;
    int f = tid >> 3, e = tid & 7;
    float s = 0.f;
    for (int b = 0; b < B_; b++) s += g_gates[(f * B_ + b) * E_ + e];
    gsum[f][e] = s;
    __syncthreads();
    if (tid < F_) {
        float mean = 0.f;
        #pragma unroll
        for (int i = 0; i < E_; i++) mean += gsum[tid][i];
        mean *= (1.f / E_);
        float ss = 0.f;
        #pragma unroll
        for (int i = 0; i < E_; i++) { float d = gsum[tid][i] - mean; ss += d * d; }
        float var = ss * (float)P_ / (float)(E_ * P_ - 1);
        cvf[tid] = var / (mean * mean + CV_EPS);
        float ent = 0.f;
        #pragma unroll
        for (int i = 0; i < E_; i++) {
            float g = gsum[tid][i] * (1.f / B_);
            ent += -g * logf(g + ENT_EPS);
        }
        entf[tid] = ent * (1.f / E_);
    }
    __syncthreads();
    if (tid == 0) {
        float a = 0.f, c = 0.f;
        for (int i = 0; i < F_; i++) { a += cvf[i]; c += entf[i]; }
        out_scalars[0] = a;
        out_scalars[1] = c;
    }
}

// ==================================================================
extern "C" void kernel_launch(void* const* d_in, const int* in_sizes, int n_in,
                              void* d_out, int out_size) {
    const float* x  = (const float*)d_in[0];
    const float* te = (const float*)d_in[1];
    const float* Wg = (const float*)d_in[2];
    const float* bg = (const float*)d_in[3];
    const float* W1 = (const float*)d_in[4];
    const float* b1 = (const float*)d_in[5];
    const float* W2 = (const float*)d_in[6];
    const float* b2 = (const float*)d_in[7];
    float* out = (float*)d_out;

    cudaFuncSetAttribute(gemm1_tc, cudaFuncAttributeMaxDynamicSharedMemorySize, G1_SMEM);
    cudaFuncSetAttribute(gemm2_tc, cudaFuncAttributeMaxDynamicSharedMemorySize, G2_SMEM);

    prep_all<<<PREP_TOTAL, 256>>>(x, W1, W2, te, Wg, bg);
    gemm1_tc<<<dim3(H_ / 128, T_ / 128, E_), 256, G1_SMEM>>>(b1);
    gemm2_tc<<<dim3(KS4, T_ / 128, E_), 256, G2_SMEM>>>();
    combine_losses<<<(T_ * P_) / 256 + 1, 256>>>(b2, out, out + (out_size - 2));
}

// round 9
// speedup vs baseline: 1.0052x; 1.0052x over previous
#include <cuda_runtime.h>
#include <cuda_fp16.h>
#include <math.h>
#include <stdint.h>

#define B_ 64
#define F_ 32
#define S_ 512
#define P_ 96
#define E_ 8
#define H_ 2048
#define T_ (F_*B_)   /* 2048 tokens */
#define ALPHA 10.0f
#define ENT_EPS 1e-8f
#define CV_EPS 1e-10f
#define KS2 2        /* gemm2 k-split */

// ---- scratch (device globals: allocation-free) ----
__device__ __half g_xf[(size_t)T_ * S_];           // 2 MB   token-major x (fp16)
__device__ __half g_w1t[(size_t)E_ * H_ * S_];     // 16.8MB W1^T [e][h][s] (fp16)
__device__ __half g_w2t[(size_t)E_ * P_ * H_];     // 3.1 MB W2^T [e][p][h] (fp16)
__device__ float  g_gates[T_ * E_];                // 64 KB
__device__ __half g_h[(size_t)E_ * T_ * H_];       // 67 MB  gelu(x@W1+b1) (fp16)
__device__ float  g_eo[(size_t)E_ * KS2 * T_ * P_];// 12.6MB expert output partials

// ==================================================================
// helpers
// ==================================================================
__device__ __forceinline__ uint32_t smem_u32(const void* p) {
    uint32_t a;
    asm("{ .reg .u64 t; cvta.to.shared.u64 t, %1; cvt.u32.u64 %0, t; }"
        : "=r"(a) : "l"(p));
    return a;
}
__device__ __forceinline__ void cp16(uint32_t saddr, const void* gaddr) {
    asm volatile("cp.async.cg.shared.global [%0], [%1], 16;"
                 :: "r"(saddr), "l"(gaddr) : "memory");
}
#define CP_COMMIT() asm volatile("cp.async.commit_group;" ::: "memory")
#define CP_WAIT2()  asm volatile("cp.async.wait_group 2;" ::: "memory")
#define CP_WAIT3()  asm volatile("cp.async.wait_group 3;" ::: "memory")

__device__ __forceinline__ void mma16(float* d, const uint32_t* a, const uint32_t* b) {
    asm volatile(
        "mma.sync.aligned.m16n8k16.row.col.f32.f16.f16.f32 "
        "{%0,%1,%2,%3}, {%4,%5,%6,%7}, {%8,%9}, {%0,%1,%2,%3};"
        : "+f"(d[0]), "+f"(d[1]), "+f"(d[2]), "+f"(d[3])
        : "r"(a[0]), "r"(a[1]), "r"(a[2]), "r"(a[3]), "r"(b[0]), "r"(b[1]));
}
__device__ __forceinline__ void ldsm4(uint32_t* r, uint32_t addr) {
    asm volatile("ldmatrix.sync.aligned.m8n8.x4.shared.b16 {%0,%1,%2,%3}, [%4];"
                 : "=r"(r[0]), "=r"(r[1]), "=r"(r[2]), "=r"(r[3]) : "r"(addr));
}
__device__ __forceinline__ float gelu_f(float v) {
    return 0.5f * v * (1.f + erff(v * 0.70710678118f));
}

// smem pitch: 40 halves (80 B) per 32-half row -> conflict-free (scalar + ldmatrix)
#define PITCH 40

// ==================================================================
// 1) fused prep + gates:
//    x->g_xf        blocks [0, 1024)
//    W1^T           blocks [1024, 9216)
//    W2^T           blocks [9216, 10752)
//    gates          blocks [10752, 11008)   (8 tokens per block)
// ==================================================================
#define PREP_XF_BLKS 1024
#define PREP_W1_BLKS (64 * 16 * E_)     /* 8192 */
#define PREP_W2_BLKS (3 * 64 * E_)      /* 1536 */
#define PREP_BLKS (PREP_XF_BLKS + PREP_W1_BLKS + PREP_W2_BLKS)
#define GATES_BLKS (T_ / 8)             /* 256 */
#define PREP_TOTAL (PREP_BLKS + GATES_BLKS)
__global__ void __launch_bounds__(256) prep_all(const float* __restrict__ x,
                                                const float* __restrict__ W1,
                                                const float* __restrict__ W2,
                                                const float* __restrict__ te,
                                                const float* __restrict__ Wg,
                                                const float* __restrict__ bg) {
    __shared__ float tile[32][33];
    __shared__ float s_wg[S_ * 9];       // gates branch only (18 KB)
    int bid = blockIdx.x;
    if (bid < PREP_XF_BLKS) {
        int t = bid * 2 + (threadIdx.x >> 7);
        int tl = threadIdx.x & 127;
        int f = t / B_, b = t - f * B_;
        const float4* src = (const float4*)(x + ((size_t)b * F_ + f) * S_);
        float4 v = src[tl];
        __half2* dst = (__half2*)(g_xf + (size_t)t * S_) + tl * 2;
        dst[0] = __floats2half2_rn(v.x, v.y);
        dst[1] = __floats2half2_rn(v.z, v.w);
    } else if (bid < PREP_XF_BLKS + PREP_W1_BLKS) {
        int i = bid - PREP_XF_BLKS;
        int e = i >> 10;                 // 64*16 per expert
        int r = i & 1023;
        int h0 = (r & 63) * 32, s0 = (r >> 6) * 32;
        int lx = threadIdx.x & 31, ly = threadIdx.x >> 5;    // 32 x 8
        #pragma unroll
        for (int k = 0; k < 32; k += 8)
            tile[ly + k][lx] = W1[((size_t)e * S_ + s0 + ly + k) * H_ + h0 + lx];
        __syncthreads();
        #pragma unroll
        for (int k = 0; k < 32; k += 8)
            g_w1t[((size_t)e * H_ + h0 + ly + k) * S_ + s0 + lx] = __float2half_rn(tile[lx][ly + k]);
    } else if (bid < PREP_BLKS) {
        int i = bid - PREP_XF_BLKS - PREP_W1_BLKS;
        int e = i / 192;
        int r = i % 192;
        int p0 = (r % 3) * 32, h0 = (r / 3) * 32;
        int lx = threadIdx.x & 31, ly = threadIdx.x >> 5;
        #pragma unroll
        for (int k = 0; k < 32; k += 8)
            tile[ly + k][lx] = W2[((size_t)e * H_ + h0 + ly + k) * P_ + p0 + lx];
        __syncthreads();
        #pragma unroll
        for (int k = 0; k < 32; k += 8)
            g_w2t[((size_t)e * P_ + p0 + ly + k) * H_ + h0 + lx] = __float2half_rn(tile[lx][ly + k]);
    } else {
        // ---- gates: 8 tokens, one warp per token ----
        const int tid = threadIdx.x;
        #pragma unroll
        for (int k = 0; k < 16; k++) {
            int idx = tid + 256 * k;     // 4096
            s_wg[(idx >> 3) * 9 + (idx & 7)] = Wg[idx];
        }
        __syncthreads();

        const int w = tid >> 5, lane = tid & 31;
        const int tok = (bid - PREP_BLKS) * 8 + w;
        const int f = tok / B_, b = tok - f * B_;
        const float* row = te + ((size_t)b * F_ + f) * S_;

        float acc[E_];
        #pragma unroll
        for (int e = 0; e < E_; e++) acc[e] = 0.f;
        #pragma unroll
        for (int c = 0; c < 16; c++) {
            float v = row[c * 32 + lane];
            const float* wp = s_wg + (c * 32 + lane) * 9;
            #pragma unroll
            for (int e = 0; e < E_; e++) acc[e] += v * wp[e];
        }
        #pragma unroll
        for (int e = 0; e < E_; e++)
            #pragma unroll
            for (int o = 16; o > 0; o >>= 1)
                acc[e] += __shfl_xor_sync(0xffffffffu, acc[e], o);

        if (lane == 0) {
            float lg[E_];
            float m1 = -1e30f, m2 = -1e30f;
            #pragma unroll
            for (int i = 0; i < E_; i++) {
                float v = acc[i] + bg[i]; lg[i] = v;
                if (v > m1) { m2 = m1; m1 = v; } else if (v > m2) m2 = v;
            }
            float kth = m2;
            float smv[E_]; float se = 0.f;
            #pragma unroll
            for (int i = 0; i < E_; i++) { smv[i] = expf(lg[i] - m1); se += smv[i]; }
            float inv = 1.f / se;
            float dec[E_]; float mx2 = -1e30f;
            #pragma unroll
            for (int i = 0; i < E_; i++) {
                float smi = smv[i] * inv;
                float d = (lg[i] < kth) ? ALPHA * logf(smi + 1.f)
                                        : ALPHA * (expf(smi) - 1.f);
                dec[i] = d; if (d > mx2) mx2 = d;
            }
            float s2 = 0.f;
            #pragma unroll
            for (int i = 0; i < E_; i++) { dec[i] = expf(dec[i] - mx2); s2 += dec[i]; }
            float inv2 = 1.f / s2;
            #pragma unroll
            for (int i = 0; i < E_; i++) g_gates[tok * E_ + i] = dec[i] * inv2;
        }
    }
}

// ==================================================================
// 4) GEMM1 (HMMA + ldmatrix): h = gelu(Xf @ W1t^T + b1)
//    block 128M x 128N x 32K, 4-stage, 8 warps (2m x 4n), warp 64x32
//    80 KB smem -> 2 CTAs/SM
// ==================================================================
#define G1_B_OFF (128 * PITCH * 2)                  /* bytes */
#define G1_STAGE_B (2 * 128 * PITCH * 2)            /* 20480 bytes */
#define G1_SMEM (4 * G1_STAGE_B)
__global__ void __launch_bounds__(256, 2) gemm1_tc(const float* __restrict__ b1) {
    extern __shared__ __half smh[];
    const int tid = threadIdx.x;
    const int wid = tid >> 5, lane = tid & 31;
    const int g = lane >> 2, q = lane & 3;
    const int e = blockIdx.z;
    const int bm = blockIdx.y * 128, bn = blockIdx.x * 128;
    const int wm = (wid & 1) * 64, wn = (wid >> 1) * 32;
    const uint32_t smb = smem_u32(smh);

    const __half* gA = g_xf + (size_t)bm * S_;
    const __half* gB = g_w1t + ((size_t)e * H_ + bn) * S_;

    uint32_t aoff[4], boff[2];
    {
        const int lrA = lane & 15, lcA = ((lane >> 4) & 1) * 8;
        #pragma unroll
        for (int i = 0; i < 4; i++)
            aoff[i] = (uint32_t)(((wm + i * 16 + lrA) * PITCH + lcA) * 2);
        const int lrB = (lane & 7) + ((lane & 16) >> 1), lcB = lane & 8;
        #pragma unroll
        for (int p = 0; p < 2; p++)
            boff[p] = (uint32_t)(G1_B_OFF + ((wn + p * 16 + lrB) * PITCH + lcB) * 2);
    }

    float acc[4][4][4];
    #pragma unroll
    for (int i = 0; i < 4; i++)
        #pragma unroll
        for (int j = 0; j < 4; j++)
            #pragma unroll
            for (int c = 0; c < 4; c++) acc[i][j][c] = 0.f;

    auto load_stage = [&](int kt, int buf) {
        const uint32_t sA = smb + (uint32_t)buf * G1_STAGE_B;
        const uint32_t sB = sA + G1_B_OFF;
        const int k0 = kt * 32;
        #pragma unroll
        for (int i = 0; i < 2; i++) {
            int idx = tid + 256 * i;
            int r = idx >> 2, c = idx & 3;
            cp16(sA + (uint32_t)r * 80u + (uint32_t)c * 16u,
                 gA + (size_t)r * S_ + k0 + c * 8);
        }
        #pragma unroll
        for (int i = 0; i < 2; i++) {
            int idx = tid + 256 * i;
            int r = idx >> 2, c = idx & 3;
            cp16(sB + (uint32_t)r * 80u + (uint32_t)c * 16u,
                 gB + (size_t)r * S_ + k0 + c * 8);
        }
    };

    const int NKT = S_ / 32;   // 16
    #pragma unroll
    for (int s = 0; s < 3; s++) { load_stage(s, s); CP_COMMIT(); }

    for (int kt = 0; kt < NKT; kt++) {
        CP_WAIT2();
        __syncthreads();
        if (kt + 3 < NKT) load_stage(kt + 3, (kt + 3) & 3);
        CP_COMMIT();
        const uint32_t sbase = smb + (uint32_t)(kt & 3) * G1_STAGE_B;
        #pragma unroll
        for (int ks = 0; ks < 2; ks++) {
            const uint32_t kboff = (uint32_t)(ks * 16 * 2);
            uint32_t a[4][4], bf[2][4];
            #pragma unroll
            for (int i = 0; i < 4; i++) ldsm4(a[i], sbase + aoff[i] + kboff);
            #pragma unroll
            for (int p = 0; p < 2; p++) ldsm4(bf[p], sbase + boff[p] + kboff);
            #pragma unroll
            for (int i = 0; i < 4; i++)
                #pragma unroll
                for (int p = 0; p < 2; p++) {
                    mma16(acc[i][2 * p + 0], a[i], &bf[p][0]);
                    mma16(acc[i][2 * p + 1], a[i], &bf[p][2]);
                }
        }
    }

    const float* bias = b1 + (size_t)e * H_ + bn;
    #pragma unroll
    for (int i = 0; i < 4; i++) {
        int r0 = bm + wm + i * 16 + g;
        #pragma unroll
        for (int j = 0; j < 4; j++) {
            int col = wn + j * 8 + 2 * q;
            float bx = bias[col], by = bias[col + 1];
            __half2 o0 = __floats2half2_rn(gelu_f(acc[i][j][0] + bx),
                                           gelu_f(acc[i][j][1] + by));
            __half2 o1 = __floats2half2_rn(gelu_f(acc[i][j][2] + bx),
                                           gelu_f(acc[i][j][3] + by));
            *(__half2*)(g_h + ((size_t)e * T_ + r0) * H_ + bn + col) = o0;
            *(__half2*)(g_h + ((size_t)e * T_ + r0 + 8) * H_ + bn + col) = o1;
        }
    }
}

// ==================================================================
// 5) GEMM2 (HMMA + ldmatrix, k-split x2): eo[ks] = h[:,ks] @ W2t^T
//    block 128M x 96N x 32K, 5-stage deep pipeline, 8 warps, warp 32x48
// ==================================================================
#define G2_STAGE_H ((128 + 96) * PITCH)
#define G2_B_OFF (128 * PITCH * 2)
#define G2_STAGE_B (G2_STAGE_H * 2)
#define G2_SMEM (5 * G2_STAGE_B)
__global__ void __launch_bounds__(256, 2) gemm2_tc(void) {
    extern __shared__ __half smh[];
    const int tid = threadIdx.x;
    const int wid = tid >> 5, lane = tid & 31;
    const int g = lane >> 2, q = lane & 3;
    const int e = blockIdx.z, ksp = blockIdx.x;
    const int bm = blockIdx.y * 128;
    const int k_base = ksp * (H_ / KS2);
    const int wm = (wid & 3) * 32, wn = (wid >> 2) * 48;
    const uint32_t smb = smem_u32(smh);

    const __half* gA = g_h + ((size_t)e * T_ + bm) * H_ + k_base;
    const __half* gB = g_w2t + (size_t)e * P_ * H_ + k_base;

    uint32_t aoff[2], boff[3];
    {
        const int lrA = lane & 15, lcA = ((lane >> 4) & 1) * 8;
        #pragma unroll
        for (int i = 0; i < 2; i++)
            aoff[i] = (uint32_t)(((wm + i * 16 + lrA) * PITCH + lcA) * 2);
        const int lrB = (lane & 7) + ((lane & 16) >> 1), lcB = lane & 8;
        #pragma unroll
        for (int p = 0; p < 3; p++)
            boff[p] = (uint32_t)(G2_B_OFF + ((wn + p * 16 + lrB) * PITCH + lcB) * 2);
    }

    float acc[2][6][4];
    #pragma unroll
    for (int i = 0; i < 2; i++)
        #pragma unroll
        for (int j = 0; j < 6; j++)
            #pragma unroll
            for (int c = 0; c < 4; c++) acc[i][j][c] = 0.f;

    auto load_stage = [&](int kt, int buf) {
        const uint32_t sA = smb + (uint32_t)buf * G2_STAGE_B;
        const uint32_t sB = sA + G2_B_OFF;
        const int k0 = kt * 32;
        #pragma unroll
        for (int i = 0; i < 2; i++) {
            int idx = tid + 256 * i;
            int r = idx >> 2, c = idx & 3;
            cp16(sA + (uint32_t)r * 80u + (uint32_t)c * 16u,
                 gA + (size_t)r * H_ + k0 + c * 8);
        }
        #pragma unroll
        for (int i = 0; i < 2; i++) {
            int idx = tid + 256 * i;
            if (idx < 384) {
                int r = idx >> 2, c = idx & 3;
                cp16(sB + (uint32_t)r * 80u + (uint32_t)c * 16u,
                     gB + (size_t)r * H_ + k0 + c * 8);
            }
        }
    };

    const int NKT = (H_ / KS2) / 32;   // 32
    #pragma unroll
    for (int s = 0; s < 4; s++) { load_stage(s, s); CP_COMMIT(); }

    int buf = 0, pbuf = 4;             // compute buffer, prefetch buffer (mod 5)
    for (int kt = 0; kt < NKT; kt++) {
        CP_WAIT3();
        __syncthreads();
        if (kt + 4 < NKT) load_stage(kt + 4, pbuf);
        CP_COMMIT();
        const uint32_t sbase = smb + (uint32_t)buf * G2_STAGE_B;
        #pragma unroll
        for (int ks = 0; ks < 2; ks++) {
            const uint32_t kboff = (uint32_t)(ks * 16 * 2);
            uint32_t a[2][4], bf[3][4];
            #pragma unroll
            for (int i = 0; i < 2; i++) ldsm4(a[i], sbase + aoff[i] + kboff);
            #pragma unroll
            for (int p = 0; p < 3; p++) ldsm4(bf[p], sbase + boff[p] + kboff);
            #pragma unroll
            for (int i = 0; i < 2; i++)
                #pragma unroll
                for (int p = 0; p < 3; p++) {
                    mma16(acc[i][2 * p + 0], a[i], &bf[p][0]);
                    mma16(acc[i][2 * p + 1], a[i], &bf[p][2]);
                }
        }
        buf = (buf == 4) ? 0 : buf + 1;
        pbuf = (pbuf == 4) ? 0 : pbuf + 1;
    }

    float* C = g_eo + (size_t)(e * KS2 + ksp) * T_ * P_;
    #pragma unroll
    for (int i = 0; i < 2; i++) {
        int r0 = bm + wm + i * 16 + g;
        #pragma unroll
        for (int j = 0; j < 6; j++) {
            int col = wn + j * 8 + 2 * q;
            float2 o0, o1;
            o0.x = acc[i][j][0]; o0.y = acc[i][j][1];
            o1.x = acc[i][j][2]; o1.y = acc[i][j][3];
            *(float2*)(C + (size_t)r0 * P_ + col) = o0;
            *(float2*)(C + (size_t)(r0 + 8) * P_ + col) = o1;
        }
    }
}

// ==================================================================
// 6) combine (float4, blocks [0,192)) + losses (block 192)
// ==================================================================
#define COMBINE_BLKS ((T_ * P_ / 4) / 256)   /* 192 */
__global__ void __launch_bounds__(256) combine_losses(const float* __restrict__ b2,
                                                      float* __restrict__ out,
                                                      float* __restrict__ out_scalars) {
    if (blockIdx.x < COMBINE_BLKS) {
        int idx = (blockIdx.x * 256 + threadIdx.x) * 4;   // element index
        int t = idx / P_, p = idx - t * P_;
        int f = t / B_, b = t - f * B_;
        float4 r = make_float4(0.f, 0.f, 0.f, 0.f);
        #pragma unroll
        for (int e = 0; e < E_; e++) {
            float4 bv = *(const float4*)(b2 + e * P_ + p);
            float4 v0 = *(const float4*)(g_eo + ((size_t)(e * KS2 + 0) * T_ + t) * P_ + p);
            float4 v1 = *(const float4*)(g_eo + ((size_t)(e * KS2 + 1) * T_ + t) * P_ + p);
            float gt = g_gates[t * E_ + e];
            r.x += gt * (bv.x + v0.x + v1.x);
            r.y += gt * (bv.y + v0.y + v1.y);
            r.z += gt * (bv.z + v0.z + v1.z);
            r.w += gt * (bv.w + v0.w + v1.w);
        }
        *(float4*)(out + ((size_t)b * F_ + f) * P_ + p) = r;
        return;
    }
    // losses block
    __shared__ float gsum[F_][E_];
    __shared__ float cvf[F_], entf[F_];
    int tid = threadIdx.x;
    int f = tid >> 3, e = tid & 7;
    float s = 0.f;
    for (int b = 0; b < B_; b++) s += g_gates[(f * B_ + b) * E_ + e];
    gsum[f][e] = s;
    __syncthreads();
    if (tid < F_) {
        float mean = 0.f;
        #pragma unroll
        for (int i = 0; i < E_; i++) mean += gsum[tid][i];
        mean *= (1.f / E_);
        float ss = 0.f;
        #pragma unroll
        for (int i = 0; i < E_; i++) { float d = gsum[tid][i] - mean; ss += d * d; }
        float var = ss * (float)P_ / (float)(E_ * P_ - 1);
        cvf[tid] = var / (mean * mean + CV_EPS);
        float ent = 0.f;
        #pragma unroll
        for (int i = 0; i < E_; i++) {
            float g = gsum[tid][i] * (1.f / B_);
            ent += -g * logf(g + ENT_EPS);
        }
        entf[tid] = ent * (1.f / E_);
    }
    __syncthreads();
    if (tid == 0) {
        float a = 0.f, c = 0.f;
        for (int i = 0; i < F_; i++) { a += cvf[i]; c += entf[i]; }
        out_scalars[0] = a;
        out_scalars[1] = c;
    }
}

// ==================================================================
extern "C" void kernel_launch(void* const* d_in, const int* in_sizes, int n_in,
                              void* d_out, int out_size) {
    const float* x  = (const float*)d_in[0];
    const float* te = (const float*)d_in[1];
    const float* Wg = (const float*)d_in[2];
    const float* bg = (const float*)d_in[3];
    const float* W1 = (const float*)d_in[4];
    const float* b1 = (const float*)d_in[5];
    const float* W2 = (const float*)d_in[6];
    const float* b2 = (const float*)d_in[7];
    float* out = (float*)d_out;

    cudaFuncSetAttribute(gemm1_tc, cudaFuncAttributeMaxDynamicSharedMemorySize, G1_SMEM);
    cudaFuncSetAttribute(gemm2_tc, cudaFuncAttributeMaxDynamicSharedMemorySize, G2_SMEM);

    prep_all<<<PREP_TOTAL, 256>>>(x, W1, W2, te, Wg, bg);
    gemm1_tc<<<dim3(H_ / 128, T_ / 128, E_), 256, G1_SMEM>>>(b1);
    gemm2_tc<<<dim3(KS2, T_ / 128, E_), 256, G2_SMEM>>>();
    combine_losses<<<COMBINE_BLKS + 1, 256>>>(b2, out, out + (out_size - 2));
}